// round 10
// baseline (speedup 1.0000x reference)
#include <cuda_runtime.h>
#include <cuda_fp16.h>
#include <cstdint>
#include <math.h>

// Problem constants (fixed shapes from reference)
#define NN 50000
#define EE 800000
#define ET (EE + NN)   // edges + self loops
#define INCH 128
#define HID 64
#define H1 4
#define OUT 64
#define F1 (H1*HID)    // 256

// ---------------- scratch (device globals; no allocation allowed) ----------
__device__ __align__(16) float  g_h1[(size_t)NN * F1];    // x @ W1 (fp32, for logits)
__device__ __align__(16) __half g_h1h[(size_t)NN * F1];   // fp16 mirror (for gather)
__device__ __align__(16) float  g_out1[(size_t)NN * F1];  // agg1 out (+b1, ELU fused)
__device__ __align__(16) float  g_h2[(size_t)NN * OUT];   // out1 @ W2
__device__ __align__(16) float  g_als1[NN * H1];
__device__ __align__(16) float  g_ald1[NN * H1];
__device__ __align__(16) float  g_als2[NN];
__device__ __align__(16) float  g_ald2[NN];
// edge decode + CSR
__device__ int g_src[ET];
__device__ int g_dst[ET];
__device__ int g_cnt[NN];      // in-degree
__device__ int g_start[NN];    // CSR row start
__device__ int g_cur[NN];      // scatter cursor
__device__ int g_bsum[64];     // scan block sums
__device__ int g_csrc[ET];     // CSR: src per slot, segmented by dst
__device__ int g_is64;

#define SCAN_B 49              // ceil(50000/1024)

__device__ __forceinline__ float lrelu(float x) { return x > 0.0f ? x : 0.2f * x; }

// ---------------- tf32 helpers ----------------
__device__ __forceinline__ uint32_t f2tf32(float x) {
    uint32_t r;
    asm("cvt.rna.tf32.f32 %0, %1;" : "=r"(r) : "f"(x));
    return r;
}

__device__ __forceinline__ void mma_tf32(float* c, const uint32_t* a, const uint32_t* b) {
    asm volatile(
        "mma.sync.aligned.m16n8k8.row.col.f32.tf32.tf32.f32 "
        "{%0,%1,%2,%3}, {%4,%5,%6,%7}, {%8,%9}, {%0,%1,%2,%3};"
        : "+f"(c[0]), "+f"(c[1]), "+f"(c[2]), "+f"(c[3])
        : "r"(a[0]), "r"(a[1]), "r"(a[2]), "r"(a[3]), "r"(b[0]), "r"(b[1]));
}

// ---------------- edge index dtype detection ----------------
__global__ void k_detect(const int* __restrict__ ei_raw) {
    if (blockIdx.x == 0 && threadIdx.x == 0) {
        int all0 = 1;
#pragma unroll
        for (int i = 1; i < 128; i += 2) all0 &= (ei_raw[i] == 0);
        g_is64 = all0;
    }
    int i = blockIdx.x * blockDim.x + threadIdx.x;
    if (i < NN) g_cnt[i] = 0;
}

// convert + clamp + histogram in one pass over edge_index
__global__ void k_convert_hist(const int* __restrict__ ei_raw) {
    int e = blockIdx.x * blockDim.x + threadIdx.x;
    if (e >= ET) return;
    int s, d;
    if (e < EE) {
        if (g_is64) {
            const long long* p = (const long long*)ei_raw;
            s = (int)p[e]; d = (int)p[EE + e];
        } else {
            s = ei_raw[e]; d = ei_raw[EE + e];
        }
        s = min(max(s, 0), NN - 1);
        d = min(max(d, 0), NN - 1);
    } else {
        s = d = e - EE;
    }
    g_src[e] = s; g_dst[e] = d;
    atomicAdd(&g_cnt[d], 1);
}

// ---------------- CSR build ----------------
__global__ void k_scan1() {
    __shared__ int sm[1024];
    int tid = threadIdx.x;
    int i = blockIdx.x * 1024 + tid;
    int v = (i < NN) ? g_cnt[i] : 0;
    sm[tid] = v;
    __syncthreads();
#pragma unroll
    for (int off = 1; off < 1024; off <<= 1) {
        int t = (tid >= off) ? sm[tid - off] : 0;
        __syncthreads();
        sm[tid] += t;
        __syncthreads();
    }
    int incl = sm[tid];
    if (i < NN) g_start[i] = incl - v;
    if (tid == 1023) g_bsum[blockIdx.x] = incl;
}

__global__ void k_scan2() {
    __shared__ int sm[64];
    int tid = threadIdx.x;
    sm[tid] = (tid < SCAN_B) ? g_bsum[tid] : 0;
    __syncthreads();
    if (tid == 0) {
        int run = 0;
        for (int i = 0; i < SCAN_B; i++) { int t = sm[i]; sm[i] = run; run += t; }
    }
    __syncthreads();
    if (tid < SCAN_B) g_bsum[tid] = sm[tid];
}

__global__ void k_scan3() {
    int i = blockIdx.x * 1024 + threadIdx.x;
    if (i < NN) {
        int st = g_start[i] + g_bsum[blockIdx.x];
        g_start[i] = st;
        g_cur[i] = st;
    }
}

__global__ void k_scatter() {
    int e = blockIdx.x * blockDim.x + threadIdx.x;
    if (e >= ET) return;
    int p = atomicAdd(&g_cur[g_dst[e]], 1);
    g_csrc[p] = g_src[e];
}

// ---------------- 3xTF32 tensor-core GEMM ----------------
// BM=128, BN=64, BK=16, 256 threads = 8 warps (4x2), warp tile 32x32.
// Optionally also writes an fp16 mirror of C (for the layer-1 gather).
#define TBM 128
#define TBN 64
#define TBK 16
#define A_STR (TBK + 1)   // 17
#define B_STR (TBN + 4)   // 68

__global__ void __launch_bounds__(256) gemm_tf32(
    const float* __restrict__ A, const float* __restrict__ B, float* __restrict__ C,
    __half* __restrict__ Ch, int M, int N, int K
) {
    __shared__ float As_hi[TBM][A_STR], As_lo[TBM][A_STR];
    __shared__ float Bs_hi[TBK][B_STR], Bs_lo[TBK][B_STR];

    const int tid    = threadIdx.x;
    const int lane   = tid & 31;
    const int warp   = tid >> 5;
    const int warp_m = warp >> 1;
    const int warp_n = warp & 1;
    const int brow   = blockIdx.y * TBM;
    const int bcol   = blockIdx.x * TBN;
    const int grp    = lane >> 2;
    const int thr4   = lane & 3;

    float c[2][4][4];
#pragma unroll
    for (int mi = 0; mi < 2; mi++)
#pragma unroll
        for (int ni = 0; ni < 4; ni++)
#pragma unroll
            for (int r = 0; r < 4; r++) c[mi][ni][r] = 0.0f;

    for (int kt = 0; kt < K; kt += TBK) {
#pragma unroll
        for (int p = 0; p < 2; p++) {
            int i = tid + p * 256;
            int r = i >> 2, c4 = (i & 3) * 4;
            float4 v = make_float4(0.f, 0.f, 0.f, 0.f);
            if (brow + r < M) v = *(const float4*)&A[(size_t)(brow + r) * K + kt + c4];
            uint32_t hx = f2tf32(v.x), hy = f2tf32(v.y), hz = f2tf32(v.z), hw = f2tf32(v.w);
            As_hi[r][c4+0] = __uint_as_float(hx);
            As_hi[r][c4+1] = __uint_as_float(hy);
            As_hi[r][c4+2] = __uint_as_float(hz);
            As_hi[r][c4+3] = __uint_as_float(hw);
            As_lo[r][c4+0] = __uint_as_float(f2tf32(v.x - __uint_as_float(hx)));
            As_lo[r][c4+1] = __uint_as_float(f2tf32(v.y - __uint_as_float(hy)));
            As_lo[r][c4+2] = __uint_as_float(f2tf32(v.z - __uint_as_float(hz)));
            As_lo[r][c4+3] = __uint_as_float(f2tf32(v.w - __uint_as_float(hw)));
        }
        {
            int r = tid >> 4, c4 = (tid & 15) * 4;
            float4 v = *(const float4*)&B[(size_t)(kt + r) * N + bcol + c4];
            uint32_t hx = f2tf32(v.x), hy = f2tf32(v.y), hz = f2tf32(v.z), hw = f2tf32(v.w);
            Bs_hi[r][c4+0] = __uint_as_float(hx);
            Bs_hi[r][c4+1] = __uint_as_float(hy);
            Bs_hi[r][c4+2] = __uint_as_float(hz);
            Bs_hi[r][c4+3] = __uint_as_float(hw);
            Bs_lo[r][c4+0] = __uint_as_float(f2tf32(v.x - __uint_as_float(hx)));
            Bs_lo[r][c4+1] = __uint_as_float(f2tf32(v.y - __uint_as_float(hy)));
            Bs_lo[r][c4+2] = __uint_as_float(f2tf32(v.z - __uint_as_float(hz)));
            Bs_lo[r][c4+3] = __uint_as_float(f2tf32(v.w - __uint_as_float(hw)));
        }
        __syncthreads();

#pragma unroll
        for (int ks = 0; ks < TBK / 8; ks++) {
            const int k0 = ks * 8;
            uint32_t a_hi[2][4], a_lo[2][4];
#pragma unroll
            for (int mi = 0; mi < 2; mi++) {
                int r0 = warp_m * 32 + mi * 16 + grp;
                int cc = k0 + thr4;
                a_hi[mi][0] = __float_as_uint(As_hi[r0    ][cc    ]);
                a_hi[mi][1] = __float_as_uint(As_hi[r0 + 8][cc    ]);
                a_hi[mi][2] = __float_as_uint(As_hi[r0    ][cc + 4]);
                a_hi[mi][3] = __float_as_uint(As_hi[r0 + 8][cc + 4]);
                a_lo[mi][0] = __float_as_uint(As_lo[r0    ][cc    ]);
                a_lo[mi][1] = __float_as_uint(As_lo[r0 + 8][cc    ]);
                a_lo[mi][2] = __float_as_uint(As_lo[r0    ][cc + 4]);
                a_lo[mi][3] = __float_as_uint(As_lo[r0 + 8][cc + 4]);
            }
            uint32_t b_hi[4][2], b_lo[4][2];
#pragma unroll
            for (int ni = 0; ni < 4; ni++) {
                int kk = k0 + thr4;
                int nn = warp_n * 32 + ni * 8 + grp;
                b_hi[ni][0] = __float_as_uint(Bs_hi[kk    ][nn]);
                b_hi[ni][1] = __float_as_uint(Bs_hi[kk + 4][nn]);
                b_lo[ni][0] = __float_as_uint(Bs_lo[kk    ][nn]);
                b_lo[ni][1] = __float_as_uint(Bs_lo[kk + 4][nn]);
            }
#pragma unroll
            for (int mi = 0; mi < 2; mi++)
#pragma unroll
                for (int ni = 0; ni < 4; ni++) {
                    mma_tf32(c[mi][ni], a_hi[mi], b_hi[ni]);
                    mma_tf32(c[mi][ni], a_hi[mi], b_lo[ni]);
                    mma_tf32(c[mi][ni], a_lo[mi], b_hi[ni]);
                }
        }
        __syncthreads();
    }

    // epilogue: fp32 store + optional fp16 mirror
#pragma unroll
    for (int mi = 0; mi < 2; mi++) {
        int r0 = brow + warp_m * 32 + mi * 16 + grp;
#pragma unroll
        for (int ni = 0; ni < 4; ni++) {
            int cc = bcol + warp_n * 32 + ni * 8 + 2 * thr4;
            if (r0 < M) {
                *(float2*)&C[(size_t)r0 * N + cc] = make_float2(c[mi][ni][0], c[mi][ni][1]);
                if (Ch) *(__half2*)&Ch[(size_t)r0 * N + cc] =
                        __floats2half2_rn(c[mi][ni][0], c[mi][ni][1]);
            }
            if (r0 + 8 < M) {
                *(float2*)&C[(size_t)(r0 + 8) * N + cc] = make_float2(c[mi][ni][2], c[mi][ni][3]);
                if (Ch) *(__half2*)&Ch[(size_t)(r0 + 8) * N + cc] =
                        __floats2half2_rn(c[mi][ni][2], c[mi][ni][3]);
            }
        }
    }
}

// ---------------- attention coefficients ----------------
__global__ void k_al1(const float* __restrict__ asrc, const float* __restrict__ adst) {
    int t = blockIdx.x * blockDim.x + threadIdx.x;   // node*4 + head
    if (t >= NN * H1) return;
    int n = t >> 2, h = t & 3;
    const float* hp = &g_h1[(size_t)n * F1 + h * HID];
    const float* ap = &asrc[h * HID];
    const float* bp = &adst[h * HID];
    float s = 0.f, d = 0.f;
#pragma unroll
    for (int i = 0; i < HID / 4; i++) {
        float4 hv = *(const float4*)&hp[i * 4];
        float4 av = *(const float4*)&ap[i * 4];
        float4 bv = *(const float4*)&bp[i * 4];
        s += hv.x * av.x + hv.y * av.y + hv.z * av.z + hv.w * av.w;
        d += hv.x * bv.x + hv.y * bv.y + hv.z * bv.z + hv.w * bv.w;
    }
    g_als1[t] = s; g_ald1[t] = d;
}

__global__ void k_al2(const float* __restrict__ asrc, const float* __restrict__ adst) {
    int n = blockIdx.x * blockDim.x + threadIdx.x;
    if (n >= NN) return;
    const float* hp = &g_h2[(size_t)n * OUT];
    float s = 0.f, d = 0.f;
#pragma unroll
    for (int i = 0; i < OUT / 4; i++) {
        float4 hv = *(const float4*)&hp[i * 4];
        float4 av = *(const float4*)&asrc[i * 4];
        float4 bv = *(const float4*)&adst[i * 4];
        s += hv.x * av.x + hv.y * av.y + hv.z * av.z + hv.w * av.w;
        d += hv.x * bv.x + hv.y * bv.y + hv.z * bv.z + hv.w * bv.w;
    }
    g_als2[n] = s; g_ald2[n] = d;
}

// ---------------- fused softmax + aggregate, layer 1 (fp16 gather) --------
__global__ void k_agg1_csr(const float* __restrict__ b1) {
    int node = blockIdx.x * 4 + (threadIdx.x >> 6);
    int g    = threadIdx.x & 63;    // 4-feature column 0..63
    int h    = g >> 4;              // head
    int lane = threadIdx.x & 31;
    int start = g_start[node];
    int deg   = g_cnt[node];
    float ald = g_ald1[node * 4 + h];
    bool leader = (lane & 15) == 0;

    float4 acc = make_float4(0.f, 0.f, 0.f, 0.f);
    float denom = 0.f;
    for (int j = 0; j < deg; j++) {
        int s = __ldg(&g_csrc[start + j]);
        float e = 0.f;
        if (leader) e = __expf(lrelu(g_als1[s * 4 + h] + ald));
        e = __shfl_sync(0xffffffffu, e, lane & 16);
        const __half2* hp = (const __half2*)&g_h1h[(size_t)s * F1 + g * 4];
        uint2 u = *(const uint2*)hp;
        float2 v0 = __half22float2(*(const __half2*)&u.x);
        float2 v1 = __half22float2(*(const __half2*)&u.y);
        acc.x += e * v0.x; acc.y += e * v0.y; acc.z += e * v1.x; acc.w += e * v1.y;
        denom += e;
    }
    float inv = 1.0f / fmaxf(denom, 1e-16f);
    float4 bv = *(const float4*)&b1[g * 4];
    float4 r;
    r.x = acc.x * inv + bv.x;
    r.y = acc.y * inv + bv.y;
    r.z = acc.z * inv + bv.z;
    r.w = acc.w * inv + bv.w;
    r.x = r.x > 0.f ? r.x : expm1f(r.x);
    r.y = r.y > 0.f ? r.y : expm1f(r.y);
    r.z = r.z > 0.f ? r.z : expm1f(r.z);
    r.w = r.w > 0.f ? r.w : expm1f(r.w);
    *(float4*)&g_out1[(size_t)node * F1 + g * 4] = r;
}

// ---------------- fused softmax + aggregate, layer 2 (fp32) ----------------
__global__ void k_agg2_csr(const float* __restrict__ b2, float* __restrict__ out) {
    int node = blockIdx.x * 16 + (threadIdx.x >> 4);
    int c    = threadIdx.x & 15;
    int lane = threadIdx.x & 31;
    int start = g_start[node];
    int deg   = g_cnt[node];
    int mdeg  = max(deg, __shfl_xor_sync(0xffffffffu, deg, 16));
    float ald = g_ald2[node];
    bool leader = (lane & 15) == 0;

    float4 acc = make_float4(0.f, 0.f, 0.f, 0.f);
    float denom = 0.f;
    for (int j = 0; j < mdeg; j++) {
        int idx = start + min(j, deg - 1);
        int s = __ldg(&g_csrc[idx]);
        float e = 0.f;
        if (leader && j < deg) e = __expf(lrelu(g_als2[s] + ald));
        e = __shfl_sync(0xffffffffu, e, lane & 16);
        float4 v = *(const float4*)&g_h2[(size_t)s * OUT + c * 4];
        acc.x += e * v.x; acc.y += e * v.y; acc.z += e * v.z; acc.w += e * v.w;
        denom += e;
    }
    float inv = 1.0f / fmaxf(denom, 1e-16f);
    float4 bv = *(const float4*)&b2[c * 4];
    float4 r;
    r.x = acc.x * inv + bv.x;
    r.y = acc.y * inv + bv.y;
    r.z = acc.z * inv + bv.z;
    r.w = acc.w * inv + bv.w;
    *(float4*)&out[(size_t)node * OUT + c * 4] = r;
}

// ---------------- launch ----------------
extern "C" void kernel_launch(void* const* d_in, const int* in_sizes, int n_in,
                              void* d_out, int out_size) {
    const float* x     = (const float*)d_in[0];
    const int*   ei    = (const int*)d_in[1];
    const float* W1    = (const float*)d_in[2];
    const float* asrc1 = (const float*)d_in[3];
    const float* adst1 = (const float*)d_in[4];
    const float* b1    = (const float*)d_in[5];
    const float* W2    = (const float*)d_in[6];
    const float* asrc2 = (const float*)d_in[7];
    const float* adst2 = (const float*)d_in[8];
    const float* b2    = (const float*)d_in[9];
    float* out = (float*)d_out;

    float*  h1;   cudaGetSymbolAddress((void**)&h1, g_h1);
    __half* h1h;  cudaGetSymbolAddress((void**)&h1h, g_h1h);
    float*  out1; cudaGetSymbolAddress((void**)&out1, g_out1);
    float*  h2;   cudaGetSymbolAddress((void**)&h2, g_h2);

    const int T = 256;

    // side stream for the CSR chain (created fresh each call; kernel_launch
    // itself runs only twice — correctness + capture — so no resource growth)
    cudaStream_t s1;
    cudaStreamCreateWithFlags(&s1, cudaStreamNonBlocking);
    cudaEvent_t ev_fork, ev_join;
    cudaEventCreateWithFlags(&ev_fork, cudaEventDisableTiming);
    cudaEventCreateWithFlags(&ev_join, cudaEventDisableTiming);

    // fork: CSR chain runs concurrently with GEMM1 + al1
    cudaEventRecord(ev_fork, 0);
    cudaStreamWaitEvent(s1, ev_fork, 0);
    k_detect<<<(NN + 1023) / 1024, 1024, 0, s1>>>(ei);
    k_convert_hist<<<(ET + T - 1) / T, T, 0, s1>>>(ei);
    k_scan1<<<SCAN_B, 1024, 0, s1>>>();
    k_scan2<<<1, 64, 0, s1>>>();
    k_scan3<<<SCAN_B, 1024, 0, s1>>>();
    k_scatter<<<(ET + T - 1) / T, T, 0, s1>>>();
    cudaEventRecord(ev_join, s1);

    // main chain (default stream)
    gemm_tf32<<<dim3(F1 / TBN, (NN + TBM - 1) / TBM), 256>>>(x, W1, h1, h1h, NN, F1, INCH);
    k_al1<<<(NN * H1 + T - 1) / T, T>>>(asrc1, adst1);

    // join CSR chain, then aggregate
    cudaStreamWaitEvent(0, ev_join, 0);
    k_agg1_csr<<<NN / 4, 256>>>(b1);

    // layer 2
    gemm_tf32<<<dim3(OUT / TBN, (NN + TBM - 1) / TBM), 256>>>(out1, W2, h2, (__half*)nullptr, NN, OUT, F1);
    k_al2<<<(NN + T - 1) / T, T>>>(asrc2, adst2);
    k_agg2_csr<<<NN / 16, 256>>>(b2, out);
}

// round 13
// speedup vs baseline: 1.0579x; 1.0579x over previous
#include <cuda_runtime.h>
#include <cuda_fp16.h>
#include <cstdint>
#include <math.h>

// Problem constants (fixed shapes from reference)
#define NN 50000
#define EE 800000
#define ET (EE + NN)   // edges + self loops
#define INCH 128
#define HID 64
#define H1 4
#define OUT 64
#define F1 (H1*HID)    // 256

// ---------------- scratch (device globals; no allocation allowed) ----------
__device__ __align__(16) float  g_h1[(size_t)NN * F1];    // x @ W1 (fp32, for logits)
__device__ __align__(16) __half g_h1h[(size_t)NN * F1];   // fp16 mirror (for gather)
__device__ __align__(16) float  g_out1[(size_t)NN * F1];  // agg1 out (+b1, ELU fused)
__device__ __align__(16) float  g_h2[(size_t)NN * OUT];   // out1 @ W2
__device__ __align__(16) float  g_als1[NN * H1];
__device__ __align__(16) float  g_ald1[NN * H1];
__device__ __align__(16) float  g_als2[NN];
__device__ __align__(16) float  g_ald2[NN];
// edge decode + CSR
__device__ int g_src[ET];
__device__ int g_dst[ET];
__device__ int g_cnt[NN];      // in-degree
__device__ int g_start[NN];    // CSR row start
__device__ int g_cur[NN];      // scatter cursor
__device__ int g_bsum[64];     // scan block sums
__device__ int g_csrc[ET];     // CSR: src per slot, segmented by dst
__device__ int g_cdst[ET];     // CSR: dst per slot
// per-slot softmax numerators
__device__ __align__(16) float g_e1[(size_t)ET * H1];
__device__ __align__(16) float g_e2[ET];
__device__ int g_is64;

#define SCAN_B 49              // ceil(50000/1024)

__device__ __forceinline__ float lrelu(float x) { return x > 0.0f ? x : 0.2f * x; }

// ---------------- tf32 helpers ----------------
__device__ __forceinline__ uint32_t f2tf32(float x) {
    uint32_t r;
    asm("cvt.rna.tf32.f32 %0, %1;" : "=r"(r) : "f"(x));
    return r;
}

__device__ __forceinline__ void mma_tf32(float* c, const uint32_t* a, const uint32_t* b) {
    asm volatile(
        "mma.sync.aligned.m16n8k8.row.col.f32.tf32.tf32.f32 "
        "{%0,%1,%2,%3}, {%4,%5,%6,%7}, {%8,%9}, {%0,%1,%2,%3};"
        : "+f"(c[0]), "+f"(c[1]), "+f"(c[2]), "+f"(c[3])
        : "r"(a[0]), "r"(a[1]), "r"(a[2]), "r"(a[3]), "r"(b[0]), "r"(b[1]));
}

// ---------------- edge index dtype detection ----------------
__global__ void k_detect(const int* __restrict__ ei_raw) {
    if (blockIdx.x == 0 && threadIdx.x == 0) {
        int all0 = 1;
#pragma unroll
        for (int i = 1; i < 128; i += 2) all0 &= (ei_raw[i] == 0);
        g_is64 = all0;
    }
    int i = blockIdx.x * blockDim.x + threadIdx.x;
    if (i < NN) g_cnt[i] = 0;
}

// convert + clamp + histogram in one pass over edge_index
__global__ void k_convert_hist(const int* __restrict__ ei_raw) {
    int e = blockIdx.x * blockDim.x + threadIdx.x;
    if (e >= ET) return;
    int s, d;
    if (e < EE) {
        if (g_is64) {
            const long long* p = (const long long*)ei_raw;
            s = (int)p[e]; d = (int)p[EE + e];
        } else {
            s = ei_raw[e]; d = ei_raw[EE + e];
        }
        s = min(max(s, 0), NN - 1);
        d = min(max(d, 0), NN - 1);
    } else {
        s = d = e - EE;
    }
    g_src[e] = s; g_dst[e] = d;
    atomicAdd(&g_cnt[d], 1);
}

// ---------------- CSR build ----------------
__global__ void k_scan1() {
    __shared__ int sm[1024];
    int tid = threadIdx.x;
    int i = blockIdx.x * 1024 + tid;
    int v = (i < NN) ? g_cnt[i] : 0;
    sm[tid] = v;
    __syncthreads();
#pragma unroll
    for (int off = 1; off < 1024; off <<= 1) {
        int t = (tid >= off) ? sm[tid - off] : 0;
        __syncthreads();
        sm[tid] += t;
        __syncthreads();
    }
    int incl = sm[tid];
    if (i < NN) g_start[i] = incl - v;
    if (tid == 1023) g_bsum[blockIdx.x] = incl;
}

__global__ void k_scan2() {
    __shared__ int sm[64];
    int tid = threadIdx.x;
    sm[tid] = (tid < SCAN_B) ? g_bsum[tid] : 0;
    __syncthreads();
    if (tid == 0) {
        int run = 0;
        for (int i = 0; i < SCAN_B; i++) { int t = sm[i]; sm[i] = run; run += t; }
    }
    __syncthreads();
    if (tid < SCAN_B) g_bsum[tid] = sm[tid];
}

__global__ void k_scan3() {
    int i = blockIdx.x * 1024 + threadIdx.x;
    if (i < NN) {
        int st = g_start[i] + g_bsum[blockIdx.x];
        g_start[i] = st;
        g_cur[i] = st;
    }
}

__global__ void k_scatter() {
    int e = blockIdx.x * blockDim.x + threadIdx.x;
    if (e >= ET) return;
    int d = g_dst[e];
    int p = atomicAdd(&g_cur[d], 1);
    g_csrc[p] = g_src[e];
    g_cdst[p] = d;
}

// ---------------- 3xTF32 tensor-core GEMM ----------------
#define TBM 128
#define TBN 64
#define TBK 16
#define A_STR (TBK + 1)   // 17
#define B_STR (TBN + 4)   // 68

__global__ void __launch_bounds__(256) gemm_tf32(
    const float* __restrict__ A, const float* __restrict__ B, float* __restrict__ C,
    __half* __restrict__ Ch, int M, int N, int K
) {
    __shared__ float As_hi[TBM][A_STR], As_lo[TBM][A_STR];
    __shared__ float Bs_hi[TBK][B_STR], Bs_lo[TBK][B_STR];

    const int tid    = threadIdx.x;
    const int lane   = tid & 31;
    const int warp   = tid >> 5;
    const int warp_m = warp >> 1;
    const int warp_n = warp & 1;
    const int brow   = blockIdx.y * TBM;
    const int bcol   = blockIdx.x * TBN;
    const int grp    = lane >> 2;
    const int thr4   = lane & 3;

    float c[2][4][4];
#pragma unroll
    for (int mi = 0; mi < 2; mi++)
#pragma unroll
        for (int ni = 0; ni < 4; ni++)
#pragma unroll
            for (int r = 0; r < 4; r++) c[mi][ni][r] = 0.0f;

    for (int kt = 0; kt < K; kt += TBK) {
#pragma unroll
        for (int p = 0; p < 2; p++) {
            int i = tid + p * 256;
            int r = i >> 2, c4 = (i & 3) * 4;
            float4 v = make_float4(0.f, 0.f, 0.f, 0.f);
            if (brow + r < M) v = *(const float4*)&A[(size_t)(brow + r) * K + kt + c4];
            uint32_t hx = f2tf32(v.x), hy = f2tf32(v.y), hz = f2tf32(v.z), hw = f2tf32(v.w);
            As_hi[r][c4+0] = __uint_as_float(hx);
            As_hi[r][c4+1] = __uint_as_float(hy);
            As_hi[r][c4+2] = __uint_as_float(hz);
            As_hi[r][c4+3] = __uint_as_float(hw);
            As_lo[r][c4+0] = __uint_as_float(f2tf32(v.x - __uint_as_float(hx)));
            As_lo[r][c4+1] = __uint_as_float(f2tf32(v.y - __uint_as_float(hy)));
            As_lo[r][c4+2] = __uint_as_float(f2tf32(v.z - __uint_as_float(hz)));
            As_lo[r][c4+3] = __uint_as_float(f2tf32(v.w - __uint_as_float(hw)));
        }
        {
            int r = tid >> 4, c4 = (tid & 15) * 4;
            float4 v = *(const float4*)&B[(size_t)(kt + r) * N + bcol + c4];
            uint32_t hx = f2tf32(v.x), hy = f2tf32(v.y), hz = f2tf32(v.z), hw = f2tf32(v.w);
            Bs_hi[r][c4+0] = __uint_as_float(hx);
            Bs_hi[r][c4+1] = __uint_as_float(hy);
            Bs_hi[r][c4+2] = __uint_as_float(hz);
            Bs_hi[r][c4+3] = __uint_as_float(hw);
            Bs_lo[r][c4+0] = __uint_as_float(f2tf32(v.x - __uint_as_float(hx)));
            Bs_lo[r][c4+1] = __uint_as_float(f2tf32(v.y - __uint_as_float(hy)));
            Bs_lo[r][c4+2] = __uint_as_float(f2tf32(v.z - __uint_as_float(hz)));
            Bs_lo[r][c4+3] = __uint_as_float(f2tf32(v.w - __uint_as_float(hw)));
        }
        __syncthreads();

#pragma unroll
        for (int ks = 0; ks < TBK / 8; ks++) {
            const int k0 = ks * 8;
            uint32_t a_hi[2][4], a_lo[2][4];
#pragma unroll
            for (int mi = 0; mi < 2; mi++) {
                int r0 = warp_m * 32 + mi * 16 + grp;
                int cc = k0 + thr4;
                a_hi[mi][0] = __float_as_uint(As_hi[r0    ][cc    ]);
                a_hi[mi][1] = __float_as_uint(As_hi[r0 + 8][cc    ]);
                a_hi[mi][2] = __float_as_uint(As_hi[r0    ][cc + 4]);
                a_hi[mi][3] = __float_as_uint(As_hi[r0 + 8][cc + 4]);
                a_lo[mi][0] = __float_as_uint(As_lo[r0    ][cc    ]);
                a_lo[mi][1] = __float_as_uint(As_lo[r0 + 8][cc    ]);
                a_lo[mi][2] = __float_as_uint(As_lo[r0    ][cc + 4]);
                a_lo[mi][3] = __float_as_uint(As_lo[r0 + 8][cc + 4]);
            }
            uint32_t b_hi[4][2], b_lo[4][2];
#pragma unroll
            for (int ni = 0; ni < 4; ni++) {
                int kk = k0 + thr4;
                int nn = warp_n * 32 + ni * 8 + grp;
                b_hi[ni][0] = __float_as_uint(Bs_hi[kk    ][nn]);
                b_hi[ni][1] = __float_as_uint(Bs_hi[kk + 4][nn]);
                b_lo[ni][0] = __float_as_uint(Bs_lo[kk    ][nn]);
                b_lo[ni][1] = __float_as_uint(Bs_lo[kk + 4][nn]);
            }
#pragma unroll
            for (int mi = 0; mi < 2; mi++)
#pragma unroll
                for (int ni = 0; ni < 4; ni++) {
                    mma_tf32(c[mi][ni], a_hi[mi], b_hi[ni]);
                    mma_tf32(c[mi][ni], a_hi[mi], b_lo[ni]);
                    mma_tf32(c[mi][ni], a_lo[mi], b_hi[ni]);
                }
        }
        __syncthreads();
    }

    // epilogue: fp32 store + optional fp16 mirror
#pragma unroll
    for (int mi = 0; mi < 2; mi++) {
        int r0 = brow + warp_m * 32 + mi * 16 + grp;
#pragma unroll
        for (int ni = 0; ni < 4; ni++) {
            int cc = bcol + warp_n * 32 + ni * 8 + 2 * thr4;
            if (r0 < M) {
                *(float2*)&C[(size_t)r0 * N + cc] = make_float2(c[mi][ni][0], c[mi][ni][1]);
                if (Ch) *(__half2*)&Ch[(size_t)r0 * N + cc] =
                        __floats2half2_rn(c[mi][ni][0], c[mi][ni][1]);
            }
            if (r0 + 8 < M) {
                *(float2*)&C[(size_t)(r0 + 8) * N + cc] = make_float2(c[mi][ni][2], c[mi][ni][3]);
                if (Ch) *(__half2*)&Ch[(size_t)(r0 + 8) * N + cc] =
                        __floats2half2_rn(c[mi][ni][2], c[mi][ni][3]);
            }
        }
    }
}

// ---------------- attention coefficients ----------------
__global__ void k_al1(const float* __restrict__ asrc, const float* __restrict__ adst) {
    int t = blockIdx.x * blockDim.x + threadIdx.x;   // node*4 + head
    if (t >= NN * H1) return;
    int n = t >> 2, h = t & 3;
    const float* hp = &g_h1[(size_t)n * F1 + h * HID];
    const float* ap = &asrc[h * HID];
    const float* bp = &adst[h * HID];
    float s = 0.f, d = 0.f;
#pragma unroll
    for (int i = 0; i < HID / 4; i++) {
        float4 hv = *(const float4*)&hp[i * 4];
        float4 av = *(const float4*)&ap[i * 4];
        float4 bv = *(const float4*)&bp[i * 4];
        s += hv.x * av.x + hv.y * av.y + hv.z * av.z + hv.w * av.w;
        d += hv.x * bv.x + hv.y * bv.y + hv.z * bv.z + hv.w * bv.w;
    }
    g_als1[t] = s; g_ald1[t] = d;
}

__global__ void k_al2(const float* __restrict__ asrc, const float* __restrict__ adst) {
    int n = blockIdx.x * blockDim.x + threadIdx.x;
    if (n >= NN) return;
    const float* hp = &g_h2[(size_t)n * OUT];
    float s = 0.f, d = 0.f;
#pragma unroll
    for (int i = 0; i < OUT / 4; i++) {
        float4 hv = *(const float4*)&hp[i * 4];
        float4 av = *(const float4*)&asrc[i * 4];
        float4 bv = *(const float4*)&adst[i * 4];
        s += hv.x * av.x + hv.y * av.y + hv.z * av.z + hv.w * av.w;
        d += hv.x * bv.x + hv.y * bv.y + hv.z * bv.z + hv.w * bv.w;
    }
    g_als2[n] = s; g_ald2[n] = d;
}

// ---------------- per-slot softmax numerators ----------------
// thread = (slot, head); linear slot reads, small scattered als/ald reads
__global__ void k_exp1() {
    int t = blockIdx.x * blockDim.x + threadIdx.x;
    if (t >= ET * H1) return;
    int slot = t >> 2, h = t & 3;
    int s = g_csrc[slot], d = g_cdst[slot];
    g_e1[t] = __expf(lrelu(g_als1[s * 4 + h] + g_ald1[d * 4 + h]));
}

__global__ void k_exp2() {
    int slot = blockIdx.x * blockDim.x + threadIdx.x;
    if (slot >= ET) return;
    int s = g_csrc[slot], d = g_cdst[slot];
    g_e2[slot] = __expf(lrelu(g_als2[s] + g_ald2[d]));
}

// ---------------- pure-gather aggregate, layer 1 (fp16 rows) --------------
// 64 threads per node; no shfl, no exp in loop; unroll-2 for MLP.
__global__ void k_agg1_csr(const float* __restrict__ b1) {
    int node = blockIdx.x * 4 + (threadIdx.x >> 6);
    int g    = threadIdx.x & 63;    // 4-feature column 0..63
    int h    = g >> 4;              // head
    int start = g_start[node];
    int deg   = g_cnt[node];

    float4 acc = make_float4(0.f, 0.f, 0.f, 0.f);
    float denom = 0.f;
    int j = 0;
    for (; j + 2 <= deg; j += 2) {
        int slot0 = start + j, slot1 = start + j + 1;
        int s0 = __ldg(&g_csrc[slot0]);
        int s1 = __ldg(&g_csrc[slot1]);
        float e0 = __ldg(&g_e1[(size_t)slot0 * 4 + h]);
        float e1 = __ldg(&g_e1[(size_t)slot1 * 4 + h]);
        uint2 u0 = *(const uint2*)&g_h1h[(size_t)s0 * F1 + g * 4];
        uint2 u1 = *(const uint2*)&g_h1h[(size_t)s1 * F1 + g * 4];
        float2 a0 = __half22float2(*(const __half2*)&u0.x);
        float2 a1 = __half22float2(*(const __half2*)&u0.y);
        float2 c0 = __half22float2(*(const __half2*)&u1.x);
        float2 c1 = __half22float2(*(const __half2*)&u1.y);
        acc.x += e0 * a0.x + e1 * c0.x;
        acc.y += e0 * a0.y + e1 * c0.y;
        acc.z += e0 * a1.x + e1 * c1.x;
        acc.w += e0 * a1.y + e1 * c1.y;
        denom += e0 + e1;
    }
    if (j < deg) {
        int slot0 = start + j;
        int s0 = __ldg(&g_csrc[slot0]);
        float e0 = __ldg(&g_e1[(size_t)slot0 * 4 + h]);
        uint2 u0 = *(const uint2*)&g_h1h[(size_t)s0 * F1 + g * 4];
        float2 a0 = __half22float2(*(const __half2*)&u0.x);
        float2 a1 = __half22float2(*(const __half2*)&u0.y);
        acc.x += e0 * a0.x; acc.y += e0 * a0.y;
        acc.z += e0 * a1.x; acc.w += e0 * a1.y;
        denom += e0;
    }
    float inv = 1.0f / fmaxf(denom, 1e-16f);
    float4 bv = *(const float4*)&b1[g * 4];
    float4 r;
    r.x = acc.x * inv + bv.x;
    r.y = acc.y * inv + bv.y;
    r.z = acc.z * inv + bv.z;
    r.w = acc.w * inv + bv.w;
    r.x = r.x > 0.f ? r.x : expm1f(r.x);
    r.y = r.y > 0.f ? r.y : expm1f(r.y);
    r.z = r.z > 0.f ? r.z : expm1f(r.z);
    r.w = r.w > 0.f ? r.w : expm1f(r.w);
    *(float4*)&g_out1[(size_t)node * F1 + g * 4] = r;
}

// ---------------- pure-gather aggregate, layer 2 (fp32 rows) --------------
__global__ void k_agg2_csr(const float* __restrict__ b2, float* __restrict__ out) {
    int node = blockIdx.x * 16 + (threadIdx.x >> 4);
    int c    = threadIdx.x & 15;
    int start = g_start[node];
    int deg   = g_cnt[node];

    float4 acc = make_float4(0.f, 0.f, 0.f, 0.f);
    float denom = 0.f;
    int j = 0;
    for (; j + 2 <= deg; j += 2) {
        int slot0 = start + j, slot1 = start + j + 1;
        int s0 = __ldg(&g_csrc[slot0]);
        int s1 = __ldg(&g_csrc[slot1]);
        float e0 = __ldg(&g_e2[slot0]);
        float e1 = __ldg(&g_e2[slot1]);
        float4 v0 = *(const float4*)&g_h2[(size_t)s0 * OUT + c * 4];
        float4 v1 = *(const float4*)&g_h2[(size_t)s1 * OUT + c * 4];
        acc.x += e0 * v0.x + e1 * v1.x;
        acc.y += e0 * v0.y + e1 * v1.y;
        acc.z += e0 * v0.z + e1 * v1.z;
        acc.w += e0 * v0.w + e1 * v1.w;
        denom += e0 + e1;
    }
    if (j < deg) {
        int slot0 = start + j;
        int s0 = __ldg(&g_csrc[slot0]);
        float e0 = __ldg(&g_e2[slot0]);
        float4 v0 = *(const float4*)&g_h2[(size_t)s0 * OUT + c * 4];
        acc.x += e0 * v0.x; acc.y += e0 * v0.y;
        acc.z += e0 * v0.z; acc.w += e0 * v0.w;
        denom += e0;
    }
    float inv = 1.0f / fmaxf(denom, 1e-16f);
    float4 bv = *(const float4*)&b2[c * 4];
    float4 r;
    r.x = acc.x * inv + bv.x;
    r.y = acc.y * inv + bv.y;
    r.z = acc.z * inv + bv.z;
    r.w = acc.w * inv + bv.w;
    *(float4*)&out[(size_t)node * OUT + c * 4] = r;
}

// ---------------- launch ----------------
extern "C" void kernel_launch(void* const* d_in, const int* in_sizes, int n_in,
                              void* d_out, int out_size) {
    const float* x     = (const float*)d_in[0];
    const int*   ei    = (const int*)d_in[1];
    const float* W1    = (const float*)d_in[2];
    const float* asrc1 = (const float*)d_in[3];
    const float* adst1 = (const float*)d_in[4];
    const float* b1    = (const float*)d_in[5];
    const float* W2    = (const float*)d_in[6];
    const float* asrc2 = (const float*)d_in[7];
    const float* adst2 = (const float*)d_in[8];
    const float* b2    = (const float*)d_in[9];
    float* out = (float*)d_out;

    float*  h1;   cudaGetSymbolAddress((void**)&h1, g_h1);
    __half* h1h;  cudaGetSymbolAddress((void**)&h1h, g_h1h);
    float*  out1; cudaGetSymbolAddress((void**)&out1, g_out1);
    float*  h2;   cudaGetSymbolAddress((void**)&h2, g_h2);

    const int T = 256;

    // edge decode + CSR build
    k_detect<<<(NN + 1023) / 1024, 1024>>>(ei);
    k_convert_hist<<<(ET + T - 1) / T, T>>>(ei);
    k_scan1<<<SCAN_B, 1024>>>();
    k_scan2<<<1, 64>>>();
    k_scan3<<<SCAN_B, 1024>>>();
    k_scatter<<<(ET + T - 1) / T, T>>>();

    // layer 1
    gemm_tf32<<<dim3(F1 / TBN, (NN + TBM - 1) / TBM), 256>>>(x, W1, h1, h1h, NN, F1, INCH);
    k_al1<<<(NN * H1 + T - 1) / T, T>>>(asrc1, adst1);
    k_exp1<<<((size_t)ET * H1 + T - 1) / T, T>>>();
    k_agg1_csr<<<NN / 4, 256>>>(b1);

    // layer 2
    gemm_tf32<<<dim3(OUT / TBN, (NN + TBM - 1) / TBM), 256>>>(out1, W2, h2, (__half*)nullptr, NN, OUT, F1);
    k_al2<<<(NN + T - 1) / T, T>>>(asrc2, adst2);
    k_exp2<<<(ET + T - 1) / T, T>>>();
    k_agg2_csr<<<NN / 16, 256>>>(b2, out);
}

// round 14
// speedup vs baseline: 1.1082x; 1.0476x over previous
#include <cuda_runtime.h>
#include <cuda_fp16.h>
#include <cstdint>
#include <math.h>

// Problem constants (fixed shapes from reference)
#define NN 50000
#define EE 800000
#define ET (EE + NN)   // edges + self loops
#define INCH 128
#define HID 64
#define H1 4
#define OUT 64
#define F1 (H1*HID)    // 256

// ---------------- scratch (device globals; no allocation allowed) ----------
__device__ __align__(16) __half g_h1h[(size_t)NN * F1];   // fp16 h1 (gather source)
__device__ __align__(16) float  g_out1[(size_t)NN * F1];  // agg1 out (+b1, ELU fused)
__device__ __align__(16) float  g_h2[(size_t)NN * OUT];   // out1 @ W2
__device__ __align__(16) float  g_w1a[8 * INCH];          // [col][k] col = h*2 + (0=src,1=dst)
__device__ __align__(16) float  g_als1[NN * H1];
__device__ __align__(16) float  g_ald1[NN * H1];
__device__ __align__(16) float  g_als2[NN];
__device__ __align__(16) float  g_ald2[NN];
// edge decode + CSR
__device__ int g_src[ET];
__device__ int g_dst[ET];
__device__ int g_cnt[NN];      // in-degree
__device__ int g_start[NN];    // CSR row start
__device__ int g_cur[NN];      // scatter cursor
__device__ int g_bsum[64];     // scan block sums
__device__ int g_csrc[ET];     // CSR: src per slot, segmented by dst
__device__ int g_cdst[ET];     // CSR: dst per slot
// per-slot softmax numerators
__device__ __align__(16) float g_e1[(size_t)ET * H1];
__device__ __align__(16) float g_e2[ET];
__device__ int g_is64;

#define SCAN_B 49              // ceil(50000/1024)

__device__ __forceinline__ float lrelu(float x) { return x > 0.0f ? x : 0.2f * x; }

// ---------------- split-fp16 mma helper ----------------
__device__ __forceinline__ void mma_f16(float* c, const uint32_t* a, const uint32_t* b) {
    asm volatile(
        "mma.sync.aligned.m16n8k16.row.col.f32.f16.f16.f32 "
        "{%0,%1,%2,%3}, {%4,%5,%6,%7}, {%8,%9}, {%0,%1,%2,%3};"
        : "+f"(c[0]), "+f"(c[1]), "+f"(c[2]), "+f"(c[3])
        : "r"(a[0]), "r"(a[1]), "r"(a[2]), "r"(a[3]), "r"(b[0]), "r"(b[1]));
}

// ---------------- edge index dtype detection ----------------
__global__ void k_detect(const int* __restrict__ ei_raw) {
    if (blockIdx.x == 0 && threadIdx.x == 0) {
        int all0 = 1;
#pragma unroll
        for (int i = 1; i < 128; i += 2) all0 &= (ei_raw[i] == 0);
        g_is64 = all0;
    }
    int i = blockIdx.x * blockDim.x + threadIdx.x;
    if (i < NN) g_cnt[i] = 0;
}

// convert + clamp + histogram in one pass over edge_index
__global__ void k_convert_hist(const int* __restrict__ ei_raw) {
    int e = blockIdx.x * blockDim.x + threadIdx.x;
    if (e >= ET) return;
    int s, d;
    if (e < EE) {
        if (g_is64) {
            const long long* p = (const long long*)ei_raw;
            s = (int)p[e]; d = (int)p[EE + e];
        } else {
            s = ei_raw[e]; d = ei_raw[EE + e];
        }
        s = min(max(s, 0), NN - 1);
        d = min(max(d, 0), NN - 1);
    } else {
        s = d = e - EE;
    }
    g_src[e] = s; g_dst[e] = d;
    atomicAdd(&g_cnt[d], 1);
}

// ---------------- CSR build ----------------
__global__ void k_scan1() {
    __shared__ int sm[1024];
    int tid = threadIdx.x;
    int i = blockIdx.x * 1024 + tid;
    int v = (i < NN) ? g_cnt[i] : 0;
    sm[tid] = v;
    __syncthreads();
#pragma unroll
    for (int off = 1; off < 1024; off <<= 1) {
        int t = (tid >= off) ? sm[tid - off] : 0;
        __syncthreads();
        sm[tid] += t;
        __syncthreads();
    }
    int incl = sm[tid];
    if (i < NN) g_start[i] = incl - v;
    if (tid == 1023) g_bsum[blockIdx.x] = incl;
}

__global__ void k_scan2() {
    __shared__ int sm[64];
    int tid = threadIdx.x;
    sm[tid] = (tid < SCAN_B) ? g_bsum[tid] : 0;
    __syncthreads();
    if (tid == 0) {
        int run = 0;
        for (int i = 0; i < SCAN_B; i++) { int t = sm[i]; sm[i] = run; run += t; }
    }
    __syncthreads();
    if (tid < SCAN_B) g_bsum[tid] = sm[tid];
}

__global__ void k_scan3() {
    int i = blockIdx.x * 1024 + threadIdx.x;
    if (i < NN) {
        int st = g_start[i] + g_bsum[blockIdx.x];
        g_start[i] = st;
        g_cur[i] = st;
    }
}

__global__ void k_scatter() {
    int e = blockIdx.x * blockDim.x + threadIdx.x;
    if (e >= ET) return;
    int d = g_dst[e];
    int p = atomicAdd(&g_cur[d], 1);
    g_csrc[p] = g_src[e];
    g_cdst[p] = d;
}

// ---------------- split-fp16 tensor-core GEMM ----------------
// BM=128, BN=64, BK=16; 256 threads = 8 warps (4x2), warp tile 32x32.
// a = a_hi + a_lo (both fp16); D += A_hi*B_hi + A_hi*B_lo + A_lo*B_hi  (fp32 acc)
// => ~2^-21 effective operand precision. B stored k-transposed for frag loads.
#define TBM 128
#define TBN 64
#define TBK 16
#define A_STR 24      // halves per A row (pad 16 -> 24)
#define B_STR 24      // halves per BsT row

__global__ void __launch_bounds__(256) gemm_f16x(
    const float* __restrict__ A, const float* __restrict__ B, float* __restrict__ C,
    __half* __restrict__ Ch, int M, int N, int K
) {
    __shared__ __half As_hi[TBM][A_STR], As_lo[TBM][A_STR];
    __shared__ __half BsT_hi[TBN][B_STR], BsT_lo[TBN][B_STR];

    const int tid    = threadIdx.x;
    const int lane   = tid & 31;
    const int warp   = tid >> 5;
    const int warp_m = warp >> 1;
    const int warp_n = warp & 1;
    const int brow   = blockIdx.y * TBM;
    const int bcol   = blockIdx.x * TBN;
    const int grp    = lane >> 2;
    const int thr4   = lane & 3;

    float c[2][4][4];
#pragma unroll
    for (int mi = 0; mi < 2; mi++)
#pragma unroll
        for (int ni = 0; ni < 4; ni++)
#pragma unroll
            for (int r = 0; r < 4; r++) c[mi][ni][r] = 0.0f;

    for (int kt = 0; kt < K; kt += TBK) {
        // A tile 128x16: 512 float4, 2 per thread
#pragma unroll
        for (int p = 0; p < 2; p++) {
            int i = tid + p * 256;
            int r = i >> 2, c4 = (i & 3) * 4;
            float4 v = make_float4(0.f, 0.f, 0.f, 0.f);
            if (brow + r < M) v = *(const float4*)&A[(size_t)(brow + r) * K + kt + c4];
            float vv[4] = {v.x, v.y, v.z, v.w};
#pragma unroll
            for (int j = 0; j < 4; j++) {
                __half hi = __float2half_rn(vv[j]);
                __half lo = __float2half_rn(vv[j] - __half2float(hi));
                As_hi[r][c4 + j] = hi;
                As_lo[r][c4 + j] = lo;
            }
        }
        // B tile 16x64 -> transposed smem [n][k]: 256 float4, 1 per thread
        {
            int r = tid >> 4, n4 = (tid & 15) * 4;
            float4 v = *(const float4*)&B[(size_t)(kt + r) * N + bcol + n4];
            float vv[4] = {v.x, v.y, v.z, v.w};
#pragma unroll
            for (int j = 0; j < 4; j++) {
                __half hi = __float2half_rn(vv[j]);
                __half lo = __float2half_rn(vv[j] - __half2float(hi));
                BsT_hi[n4 + j][r] = hi;
                BsT_lo[n4 + j][r] = lo;
            }
        }
        __syncthreads();

        // one k16 step per tile
        uint32_t a_hi[2][4], a_lo[2][4];
#pragma unroll
        for (int mi = 0; mi < 2; mi++) {
            int r0 = warp_m * 32 + mi * 16 + grp;
            a_hi[mi][0] = *(const uint32_t*)&As_hi[r0    ][thr4 * 2];
            a_hi[mi][1] = *(const uint32_t*)&As_hi[r0 + 8][thr4 * 2];
            a_hi[mi][2] = *(const uint32_t*)&As_hi[r0    ][8 + thr4 * 2];
            a_hi[mi][3] = *(const uint32_t*)&As_hi[r0 + 8][8 + thr4 * 2];
            a_lo[mi][0] = *(const uint32_t*)&As_lo[r0    ][thr4 * 2];
            a_lo[mi][1] = *(const uint32_t*)&As_lo[r0 + 8][thr4 * 2];
            a_lo[mi][2] = *(const uint32_t*)&As_lo[r0    ][8 + thr4 * 2];
            a_lo[mi][3] = *(const uint32_t*)&As_lo[r0 + 8][8 + thr4 * 2];
        }
        uint32_t b_hi[4][2], b_lo[4][2];
#pragma unroll
        for (int ni = 0; ni < 4; ni++) {
            int nn = warp_n * 32 + ni * 8 + grp;
            b_hi[ni][0] = *(const uint32_t*)&BsT_hi[nn][thr4 * 2];
            b_hi[ni][1] = *(const uint32_t*)&BsT_hi[nn][8 + thr4 * 2];
            b_lo[ni][0] = *(const uint32_t*)&BsT_lo[nn][thr4 * 2];
            b_lo[ni][1] = *(const uint32_t*)&BsT_lo[nn][8 + thr4 * 2];
        }
#pragma unroll
        for (int mi = 0; mi < 2; mi++)
#pragma unroll
            for (int ni = 0; ni < 4; ni++) {
                mma_f16(c[mi][ni], a_hi[mi], b_hi[ni]);
                mma_f16(c[mi][ni], a_hi[mi], b_lo[ni]);
                mma_f16(c[mi][ni], a_lo[mi], b_hi[ni]);
            }
        __syncthreads();
    }

    // epilogue: optional fp32 store, optional fp16 mirror
#pragma unroll
    for (int mi = 0; mi < 2; mi++) {
        int r0 = brow + warp_m * 32 + mi * 16 + grp;
#pragma unroll
        for (int ni = 0; ni < 4; ni++) {
            int cc = bcol + warp_n * 32 + ni * 8 + 2 * thr4;
            if (r0 < M) {
                if (C)  *(float2*)&C[(size_t)r0 * N + cc] = make_float2(c[mi][ni][0], c[mi][ni][1]);
                if (Ch) *(__half2*)&Ch[(size_t)r0 * N + cc] =
                        __floats2half2_rn(c[mi][ni][0], c[mi][ni][1]);
            }
            if (r0 + 8 < M) {
                if (C)  *(float2*)&C[(size_t)(r0 + 8) * N + cc] = make_float2(c[mi][ni][2], c[mi][ni][3]);
                if (Ch) *(__half2*)&Ch[(size_t)(r0 + 8) * N + cc] =
                        __floats2half2_rn(c[mi][ni][2], c[mi][ni][3]);
            }
        }
    }
}

// ---------------- attention coefficient projection ----------------
// W1a[col][k] = sum_f W1[k, h*64+f] * a[h][f],  col = h*2 + (0=src, 1=dst)
__global__ void k_w1a(const float* __restrict__ W1,
                      const float* __restrict__ asrc, const float* __restrict__ adst) {
    int tid = threadIdx.x;          // 1024 = 128 k x 8 col
    int k = tid >> 3, col = tid & 7;
    int h = col >> 1;
    const float* av = (col & 1) ? adst : asrc;
    float s = 0.f;
#pragma unroll
    for (int f = 0; f < HID; f++)
        s += W1[k * F1 + h * HID + f] * av[h * HID + f];
    g_w1a[col * INCH + k] = s;
}

// als1/ald1 directly from x:  als1[n,h] = x[n,:] . W1a[h*2]
__global__ void k_al1x(const float* __restrict__ x) {
    __shared__ __align__(16) float sw[8][140];
    int tid = threadIdx.x;
    for (int i = tid; i < 8 * INCH; i += 256)
        sw[i >> 7][i & 127] = g_w1a[i];
    __syncthreads();
    int node = blockIdx.x * 32 + (tid >> 3);
    int col  = tid & 7;
    if (node >= NN) return;
    float acc = 0.f;
#pragma unroll
    for (int k4 = 0; k4 < INCH / 4; k4++) {
        float4 xv = *(const float4*)&x[(size_t)node * INCH + k4 * 4];
        float4 wv = *(const float4*)&sw[col][k4 * 4];
        acc += xv.x * wv.x + xv.y * wv.y + xv.z * wv.z + xv.w * wv.w;
    }
    int h = col >> 1;
    if (col & 1) g_ald1[node * 4 + h] = acc;
    else         g_als1[node * 4 + h] = acc;
}

__global__ void k_al2(const float* __restrict__ asrc, const float* __restrict__ adst) {
    int n = blockIdx.x * blockDim.x + threadIdx.x;
    if (n >= NN) return;
    const float* hp = &g_h2[(size_t)n * OUT];
    float s = 0.f, d = 0.f;
#pragma unroll
    for (int i = 0; i < OUT / 4; i++) {
        float4 hv = *(const float4*)&hp[i * 4];
        float4 av = *(const float4*)&asrc[i * 4];
        float4 bv = *(const float4*)&adst[i * 4];
        s += hv.x * av.x + hv.y * av.y + hv.z * av.z + hv.w * av.w;
        d += hv.x * bv.x + hv.y * bv.y + hv.z * bv.z + hv.w * bv.w;
    }
    g_als2[n] = s; g_ald2[n] = d;
}

// ---------------- per-slot softmax numerators ----------------
__global__ void k_exp1() {
    int t = blockIdx.x * blockDim.x + threadIdx.x;
    if (t >= ET * H1) return;
    int slot = t >> 2, h = t & 3;
    int s = g_csrc[slot], d = g_cdst[slot];
    g_e1[t] = __expf(lrelu(g_als1[s * 4 + h] + g_ald1[d * 4 + h]));
}

__global__ void k_exp2() {
    int slot = blockIdx.x * blockDim.x + threadIdx.x;
    if (slot >= ET) return;
    int s = g_csrc[slot], d = g_cdst[slot];
    g_e2[slot] = __expf(lrelu(g_als2[s] + g_ald2[d]));
}

// ---------------- pure-gather aggregate, layer 1 (fp16 rows) --------------
__global__ void k_agg1_csr(const float* __restrict__ b1) {
    int node = blockIdx.x * 4 + (threadIdx.x >> 6);
    int g    = threadIdx.x & 63;    // 4-feature column 0..63
    int h    = g >> 4;              // head
    int start = g_start[node];
    int deg   = g_cnt[node];

    float4 acc = make_float4(0.f, 0.f, 0.f, 0.f);
    float denom = 0.f;
    int j = 0;
    for (; j + 2 <= deg; j += 2) {
        int slot0 = start + j, slot1 = start + j + 1;
        int s0 = __ldg(&g_csrc[slot0]);
        int s1 = __ldg(&g_csrc[slot1]);
        float e0 = __ldg(&g_e1[(size_t)slot0 * 4 + h]);
        float e1 = __ldg(&g_e1[(size_t)slot1 * 4 + h]);
        uint2 u0 = *(const uint2*)&g_h1h[(size_t)s0 * F1 + g * 4];
        uint2 u1 = *(const uint2*)&g_h1h[(size_t)s1 * F1 + g * 4];
        float2 a0 = __half22float2(*(const __half2*)&u0.x);
        float2 a1 = __half22float2(*(const __half2*)&u0.y);
        float2 c0 = __half22float2(*(const __half2*)&u1.x);
        float2 c1 = __half22float2(*(const __half2*)&u1.y);
        acc.x += e0 * a0.x + e1 * c0.x;
        acc.y += e0 * a0.y + e1 * c0.y;
        acc.z += e0 * a1.x + e1 * c1.x;
        acc.w += e0 * a1.y + e1 * c1.y;
        denom += e0 + e1;
    }
    if (j < deg) {
        int slot0 = start + j;
        int s0 = __ldg(&g_csrc[slot0]);
        float e0 = __ldg(&g_e1[(size_t)slot0 * 4 + h]);
        uint2 u0 = *(const uint2*)&g_h1h[(size_t)s0 * F1 + g * 4];
        float2 a0 = __half22float2(*(const __half2*)&u0.x);
        float2 a1 = __half22float2(*(const __half2*)&u0.y);
        acc.x += e0 * a0.x; acc.y += e0 * a0.y;
        acc.z += e0 * a1.x; acc.w += e0 * a1.y;
        denom += e0;
    }
    float inv = 1.0f / fmaxf(denom, 1e-16f);
    float4 bv = *(const float4*)&b1[g * 4];
    float4 r;
    r.x = acc.x * inv + bv.x;
    r.y = acc.y * inv + bv.y;
    r.z = acc.z * inv + bv.z;
    r.w = acc.w * inv + bv.w;
    r.x = r.x > 0.f ? r.x : expm1f(r.x);
    r.y = r.y > 0.f ? r.y : expm1f(r.y);
    r.z = r.z > 0.f ? r.z : expm1f(r.z);
    r.w = r.w > 0.f ? r.w : expm1f(r.w);
    *(float4*)&g_out1[(size_t)node * F1 + g * 4] = r;
}

// ---------------- pure-gather aggregate, layer 2 (fp32 rows) --------------
__global__ void k_agg2_csr(const float* __restrict__ b2, float* __restrict__ out) {
    int node = blockIdx.x * 16 + (threadIdx.x >> 4);
    int c    = threadIdx.x & 15;
    int start = g_start[node];
    int deg   = g_cnt[node];

    float4 acc = make_float4(0.f, 0.f, 0.f, 0.f);
    float denom = 0.f;
    int j = 0;
    for (; j + 2 <= deg; j += 2) {
        int slot0 = start + j, slot1 = start + j + 1;
        int s0 = __ldg(&g_csrc[slot0]);
        int s1 = __ldg(&g_csrc[slot1]);
        float e0 = __ldg(&g_e2[slot0]);
        float e1 = __ldg(&g_e2[slot1]);
        float4 v0 = *(const float4*)&g_h2[(size_t)s0 * OUT + c * 4];
        float4 v1 = *(const float4*)&g_h2[(size_t)s1 * OUT + c * 4];
        acc.x += e0 * v0.x + e1 * v1.x;
        acc.y += e0 * v0.y + e1 * v1.y;
        acc.z += e0 * v0.z + e1 * v1.z;
        acc.w += e0 * v0.w + e1 * v1.w;
        denom += e0 + e1;
    }
    if (j < deg) {
        int slot0 = start + j;
        int s0 = __ldg(&g_csrc[slot0]);
        float e0 = __ldg(&g_e2[slot0]);
        float4 v0 = *(const float4*)&g_h2[(size_t)s0 * OUT + c * 4];
        acc.x += e0 * v0.x; acc.y += e0 * v0.y;
        acc.z += e0 * v0.z; acc.w += e0 * v0.w;
        denom += e0;
    }
    float inv = 1.0f / fmaxf(denom, 1e-16f);
    float4 bv = *(const float4*)&b2[c * 4];
    float4 r;
    r.x = acc.x * inv + bv.x;
    r.y = acc.y * inv + bv.y;
    r.z = acc.z * inv + bv.z;
    r.w = acc.w * inv + bv.w;
    *(float4*)&out[(size_t)node * OUT + c * 4] = r;
}

// ---------------- launch ----------------
extern "C" void kernel_launch(void* const* d_in, const int* in_sizes, int n_in,
                              void* d_out, int out_size) {
    const float* x     = (const float*)d_in[0];
    const int*   ei    = (const int*)d_in[1];
    const float* W1    = (const float*)d_in[2];
    const float* asrc1 = (const float*)d_in[3];
    const float* adst1 = (const float*)d_in[4];
    const float* b1    = (const float*)d_in[5];
    const float* W2    = (const float*)d_in[6];
    const float* asrc2 = (const float*)d_in[7];
    const float* adst2 = (const float*)d_in[8];
    const float* b2    = (const float*)d_in[9];
    float* out = (float*)d_out;

    __half* h1h;  cudaGetSymbolAddress((void**)&h1h, g_h1h);
    float*  out1; cudaGetSymbolAddress((void**)&out1, g_out1);
    float*  h2;   cudaGetSymbolAddress((void**)&h2, g_h2);

    const int T = 256;

    // edge decode + CSR build
    k_detect<<<(NN + 1023) / 1024, 1024>>>(ei);
    k_convert_hist<<<(ET + T - 1) / T, T>>>(ei);
    k_scan1<<<SCAN_B, 1024>>>();
    k_scan2<<<1, 64>>>();
    k_scan3<<<SCAN_B, 1024>>>();
    k_scatter<<<(ET + T - 1) / T, T>>>();

    // layer 1: GEMM writes only the fp16 mirror; logits come straight from x
    k_w1a<<<1, 1024>>>(W1, asrc1, adst1);
    gemm_f16x<<<dim3(F1 / TBN, (NN + TBM - 1) / TBM), 256>>>(x, W1, (float*)nullptr, h1h, NN, F1, INCH);
    k_al1x<<<(NN + 31) / 32, 256>>>(x);
    k_exp1<<<((size_t)ET * H1 + T - 1) / T, T>>>();
    k_agg1_csr<<<NN / 4, 256>>>(b1);

    // layer 2
    gemm_f16x<<<dim3(OUT / TBN, (NN + TBM - 1) / TBM), 256>>>(out1, W2, h2, (__half*)nullptr, NN, OUT, F1);
    k_al2<<<(NN + T - 1) / T, T>>>(asrc2, adst2);
    k_exp2<<<(ET + T - 1) / T, T>>>();
    k_agg2_csr<<<NN / 16, 256>>>(b2, out);
}

// round 16
// speedup vs baseline: 1.1210x; 1.0115x over previous
#include <cuda_runtime.h>
#include <cuda_fp16.h>
#include <cstdint>
#include <math.h>

// Problem constants (fixed shapes from reference)
#define NN 50000
#define EE 800000
#define ET (EE + NN)   // edges + self loops
#define INCH 128
#define HID 64
#define H1 4
#define OUT 64
#define F1 (H1*HID)    // 256

// ---------------- scratch (device globals; no allocation allowed) ----------
__device__ __align__(16) __half g_h1h[(size_t)NN * F1];   // fp16 h1 (gather source)
__device__ __align__(16) float  g_out1[(size_t)NN * F1];  // agg1 out (+b1, ELU fused)
__device__ __align__(16) float  g_h2[(size_t)NN * OUT];   // out1 @ W2
__device__ __align__(16) float  g_w1a[8 * INCH];          // [col][k] col = h*2 + (0=src,1=dst)
__device__ __align__(16) float  g_als1[NN * H1];
__device__ __align__(16) float  g_ald1[NN * H1];
__device__ __align__(16) float  g_als2[NN];
__device__ __align__(16) float  g_ald2[NN];
// edge decode + CSR
__device__ int g_src[ET];
__device__ int g_dst[ET];
__device__ int g_cnt[NN];      // in-degree
__device__ int g_start[NN];    // CSR row start
__device__ int g_cur[NN];      // scatter cursor
__device__ int g_csrc[ET];     // CSR: src per slot, segmented by dst
__device__ int g_cdst[ET];     // CSR: dst per slot
// per-slot softmax numerators
__device__ __align__(16) float g_e1[(size_t)ET * H1];
__device__ __align__(16) float g_e2[ET];
__device__ int g_is64;
// single-pass scan state
#define SCAN_B 49              // ceil(50000/1024)
__device__ int g_tot[SCAN_B];
__device__ volatile int g_flag[SCAN_B];

__device__ __forceinline__ float lrelu(float x) { return x > 0.0f ? x : 0.2f * x; }

// ---------------- split-fp16 mma helper ----------------
__device__ __forceinline__ void mma_f16(float* c, const uint32_t* a, const uint32_t* b) {
    asm volatile(
        "mma.sync.aligned.m16n8k16.row.col.f32.f16.f16.f32 "
        "{%0,%1,%2,%3}, {%4,%5,%6,%7}, {%8,%9}, {%0,%1,%2,%3};"
        : "+f"(c[0]), "+f"(c[1]), "+f"(c[2]), "+f"(c[3])
        : "r"(a[0]), "r"(a[1]), "r"(a[2]), "r"(a[3]), "r"(b[0]), "r"(b[1]));
}

// ---------------- edge index dtype detection + state reset ----------------
__global__ void k_detect(const int* __restrict__ ei_raw) {
    if (blockIdx.x == 0 && threadIdx.x == 0) {
        int all0 = 1;
#pragma unroll
        for (int i = 1; i < 128; i += 2) all0 &= (ei_raw[i] == 0);
        g_is64 = all0;
    }
    int i = blockIdx.x * blockDim.x + threadIdx.x;
    if (i < NN) g_cnt[i] = 0;
    if (i < SCAN_B) { g_flag[i] = 0; }   // reset scan flags every replay
}

// convert + clamp + histogram in one pass over edge_index
__global__ void k_convert_hist(const int* __restrict__ ei_raw) {
    int e = blockIdx.x * blockDim.x + threadIdx.x;
    if (e >= ET) return;
    int s, d;
    if (e < EE) {
        if (g_is64) {
            const long long* p = (const long long*)ei_raw;
            s = (int)p[e]; d = (int)p[EE + e];
        } else {
            s = ei_raw[e]; d = ei_raw[EE + e];
        }
        s = min(max(s, 0), NN - 1);
        d = min(max(d, 0), NN - 1);
    } else {
        s = d = e - EE;
    }
    g_src[e] = s; g_dst[e] = d;
    atomicAdd(&g_cnt[d], 1);
}

// ---------------- single-pass scan (49 blocks, all resident) --------------
__global__ void __launch_bounds__(1024) k_scan_all() {
    __shared__ int sm[1024];
    __shared__ int s_tot[SCAN_B];
    const int tid = threadIdx.x;
    const int b   = blockIdx.x;
    const int i   = b * 1024 + tid;
    int v = (i < NN) ? g_cnt[i] : 0;
    sm[tid] = v;
    __syncthreads();
#pragma unroll
    for (int off = 1; off < 1024; off <<= 1) {
        int t = (tid >= off) ? sm[tid - off] : 0;
        __syncthreads();
        sm[tid] += t;
        __syncthreads();
    }
    int local_excl = sm[tid] - v;
    // publish block total
    if (tid == 1023) {
        g_tot[b] = sm[1023];
        __threadfence();
        g_flag[b] = 1;
    }
    // gather all block totals (blocks are all resident: safe spin)
    if (tid < SCAN_B) {
        while (g_flag[tid] == 0) {}
        s_tot[tid] = g_tot[tid];
    }
    __syncthreads();
    // prefix of totals for blocks < b (cheap: <=48 shared loads per thread,
    // but do it once in shared by thread 0 then broadcast)
    __shared__ int s_prefix;
    if (tid == 0) {
        int run = 0;
        for (int j = 0; j < b; j++) run += s_tot[j];
        s_prefix = run;
    }
    __syncthreads();
    if (i < NN) {
        int st = local_excl + s_prefix;
        g_start[i] = st;
        g_cur[i] = st;
    }
}

// ---------------- scatter + fused exp1 ----------------
// requires als1/ald1 (from k_al1x) — run after it.
__global__ void k_scatter_exp1() {
    int e = blockIdx.x * blockDim.x + threadIdx.x;
    if (e >= ET) return;
    int s = g_src[e], d = g_dst[e];
    int p = atomicAdd(&g_cur[d], 1);
    g_csrc[p] = s;
    g_cdst[p] = d;
    float4 as4 = *(const float4*)&g_als1[s * 4];
    float4 ad4 = *(const float4*)&g_ald1[d * 4];
    float4 ev;
    ev.x = __expf(lrelu(as4.x + ad4.x));
    ev.y = __expf(lrelu(as4.y + ad4.y));
    ev.z = __expf(lrelu(as4.z + ad4.z));
    ev.w = __expf(lrelu(as4.w + ad4.w));
    *(float4*)&g_e1[(size_t)p * 4] = ev;
}

// ---------------- split-fp16 tensor-core GEMM ----------------
#define TBM 128
#define TBN 64
#define TBK 16
#define A_STR 24      // halves per A row (pad 16 -> 24)
#define B_STR 24      // halves per BsT row

__global__ void __launch_bounds__(256) gemm_f16x(
    const float* __restrict__ A, const float* __restrict__ B, float* __restrict__ C,
    __half* __restrict__ Ch, int M, int N, int K
) {
    __shared__ __half As_hi[TBM][A_STR], As_lo[TBM][A_STR];
    __shared__ __half BsT_hi[TBN][B_STR], BsT_lo[TBN][B_STR];

    const int tid    = threadIdx.x;
    const int lane   = tid & 31;
    const int warp   = tid >> 5;
    const int warp_m = warp >> 1;
    const int warp_n = warp & 1;
    const int brow   = blockIdx.y * TBM;
    const int bcol   = blockIdx.x * TBN;
    const int grp    = lane >> 2;
    const int thr4   = lane & 3;

    float c[2][4][4];
#pragma unroll
    for (int mi = 0; mi < 2; mi++)
#pragma unroll
        for (int ni = 0; ni < 4; ni++)
#pragma unroll
            for (int r = 0; r < 4; r++) c[mi][ni][r] = 0.0f;

    for (int kt = 0; kt < K; kt += TBK) {
#pragma unroll
        for (int p = 0; p < 2; p++) {
            int i = tid + p * 256;
            int r = i >> 2, c4 = (i & 3) * 4;
            float4 v = make_float4(0.f, 0.f, 0.f, 0.f);
            if (brow + r < M) v = *(const float4*)&A[(size_t)(brow + r) * K + kt + c4];
            float vv[4] = {v.x, v.y, v.z, v.w};
#pragma unroll
            for (int j = 0; j < 4; j++) {
                __half hi = __float2half_rn(vv[j]);
                __half lo = __float2half_rn(vv[j] - __half2float(hi));
                As_hi[r][c4 + j] = hi;
                As_lo[r][c4 + j] = lo;
            }
        }
        {
            int r = tid >> 4, n4 = (tid & 15) * 4;
            float4 v = *(const float4*)&B[(size_t)(kt + r) * N + bcol + n4];
            float vv[4] = {v.x, v.y, v.z, v.w};
#pragma unroll
            for (int j = 0; j < 4; j++) {
                __half hi = __float2half_rn(vv[j]);
                __half lo = __float2half_rn(vv[j] - __half2float(hi));
                BsT_hi[n4 + j][r] = hi;
                BsT_lo[n4 + j][r] = lo;
            }
        }
        __syncthreads();

        uint32_t a_hi[2][4], a_lo[2][4];
#pragma unroll
        for (int mi = 0; mi < 2; mi++) {
            int r0 = warp_m * 32 + mi * 16 + grp;
            a_hi[mi][0] = *(const uint32_t*)&As_hi[r0    ][thr4 * 2];
            a_hi[mi][1] = *(const uint32_t*)&As_hi[r0 + 8][thr4 * 2];
            a_hi[mi][2] = *(const uint32_t*)&As_hi[r0    ][8 + thr4 * 2];
            a_hi[mi][3] = *(const uint32_t*)&As_hi[r0 + 8][8 + thr4 * 2];
            a_lo[mi][0] = *(const uint32_t*)&As_lo[r0    ][thr4 * 2];
            a_lo[mi][1] = *(const uint32_t*)&As_lo[r0 + 8][thr4 * 2];
            a_lo[mi][2] = *(const uint32_t*)&As_lo[r0    ][8 + thr4 * 2];
            a_lo[mi][3] = *(const uint32_t*)&As_lo[r0 + 8][8 + thr4 * 2];
        }
        uint32_t b_hi[4][2], b_lo[4][2];
#pragma unroll
        for (int ni = 0; ni < 4; ni++) {
            int nn = warp_n * 32 + ni * 8 + grp;
            b_hi[ni][0] = *(const uint32_t*)&BsT_hi[nn][thr4 * 2];
            b_hi[ni][1] = *(const uint32_t*)&BsT_hi[nn][8 + thr4 * 2];
            b_lo[ni][0] = *(const uint32_t*)&BsT_lo[nn][thr4 * 2];
            b_lo[ni][1] = *(const uint32_t*)&BsT_lo[nn][8 + thr4 * 2];
        }
#pragma unroll
        for (int mi = 0; mi < 2; mi++)
#pragma unroll
            for (int ni = 0; ni < 4; ni++) {
                mma_f16(c[mi][ni], a_hi[mi], b_hi[ni]);
                mma_f16(c[mi][ni], a_hi[mi], b_lo[ni]);
                mma_f16(c[mi][ni], a_lo[mi], b_hi[ni]);
            }
        __syncthreads();
    }

#pragma unroll
    for (int mi = 0; mi < 2; mi++) {
        int r0 = brow + warp_m * 32 + mi * 16 + grp;
#pragma unroll
        for (int ni = 0; ni < 4; ni++) {
            int cc = bcol + warp_n * 32 + ni * 8 + 2 * thr4;
            if (r0 < M) {
                if (C)  *(float2*)&C[(size_t)r0 * N + cc] = make_float2(c[mi][ni][0], c[mi][ni][1]);
                if (Ch) *(__half2*)&Ch[(size_t)r0 * N + cc] =
                        __floats2half2_rn(c[mi][ni][0], c[mi][ni][1]);
            }
            if (r0 + 8 < M) {
                if (C)  *(float2*)&C[(size_t)(r0 + 8) * N + cc] = make_float2(c[mi][ni][2], c[mi][ni][3]);
                if (Ch) *(__half2*)&Ch[(size_t)(r0 + 8) * N + cc] =
                        __floats2half2_rn(c[mi][ni][2], c[mi][ni][3]);
            }
        }
    }
}

// ---------------- attention coefficient projection ----------------
__global__ void k_w1a(const float* __restrict__ W1,
                      const float* __restrict__ asrc, const float* __restrict__ adst) {
    int tid = threadIdx.x;          // 1024 = 128 k x 8 col
    int k = tid >> 3, col = tid & 7;
    int h = col >> 1;
    const float* av = (col & 1) ? adst : asrc;
    float s = 0.f;
#pragma unroll
    for (int f = 0; f < HID; f++)
        s += W1[k * F1 + h * HID + f] * av[h * HID + f];
    g_w1a[col * INCH + k] = s;
}

__global__ void k_al1x(const float* __restrict__ x) {
    __shared__ __align__(16) float sw[8][140];
    int tid = threadIdx.x;
    for (int i = tid; i < 8 * INCH; i += 256)
        sw[i >> 7][i & 127] = g_w1a[i];
    __syncthreads();
    int node = blockIdx.x * 32 + (tid >> 3);
    int col  = tid & 7;
    if (node >= NN) return;
    float acc = 0.f;
#pragma unroll
    for (int k4 = 0; k4 < INCH / 4; k4++) {
        float4 xv = *(const float4*)&x[(size_t)node * INCH + k4 * 4];
        float4 wv = *(const float4*)&sw[col][k4 * 4];
        acc += xv.x * wv.x + xv.y * wv.y + xv.z * wv.z + xv.w * wv.w;
    }
    int h = col >> 1;
    if (col & 1) g_ald1[node * 4 + h] = acc;
    else         g_als1[node * 4 + h] = acc;
}

__global__ void k_al2(const float* __restrict__ asrc, const float* __restrict__ adst) {
    int n = blockIdx.x * blockDim.x + threadIdx.x;
    if (n >= NN) return;
    const float* hp = &g_h2[(size_t)n * OUT];
    float s = 0.f, d = 0.f;
#pragma unroll
    for (int i = 0; i < OUT / 4; i++) {
        float4 hv = *(const float4*)&hp[i * 4];
        float4 av = *(const float4*)&asrc[i * 4];
        float4 bv = *(const float4*)&adst[i * 4];
        s += hv.x * av.x + hv.y * av.y + hv.z * av.z + hv.w * av.w;
        d += hv.x * bv.x + hv.y * bv.y + hv.z * bv.z + hv.w * bv.w;
    }
    g_als2[n] = s; g_ald2[n] = d;
}

__global__ void k_exp2() {
    int slot = blockIdx.x * blockDim.x + threadIdx.x;
    if (slot >= ET) return;
    int s = g_csrc[slot], d = g_cdst[slot];
    g_e2[slot] = __expf(lrelu(g_als2[s] + g_ald2[d]));
}

// ---------------- pure-gather aggregate, layer 1 (fp16 rows) --------------
__global__ void k_agg1_csr(const float* __restrict__ b1) {
    int node = blockIdx.x * 4 + (threadIdx.x >> 6);
    int g    = threadIdx.x & 63;    // 4-feature column 0..63
    int h    = g >> 4;              // head
    int start = g_start[node];
    int deg   = g_cnt[node];

    float4 acc = make_float4(0.f, 0.f, 0.f, 0.f);
    float denom = 0.f;
    int j = 0;
    for (; j + 2 <= deg; j += 2) {
        int slot0 = start + j, slot1 = start + j + 1;
        int s0 = __ldg(&g_csrc[slot0]);
        int s1 = __ldg(&g_csrc[slot1]);
        float e0 = __ldg(&g_e1[(size_t)slot0 * 4 + h]);
        float e1 = __ldg(&g_e1[(size_t)slot1 * 4 + h]);
        uint2 u0 = *(const uint2*)&g_h1h[(size_t)s0 * F1 + g * 4];
        uint2 u1 = *(const uint2*)&g_h1h[(size_t)s1 * F1 + g * 4];
        float2 a0 = __half22float2(*(const __half2*)&u0.x);
        float2 a1 = __half22float2(*(const __half2*)&u0.y);
        float2 c0 = __half22float2(*(const __half2*)&u1.x);
        float2 c1 = __half22float2(*(const __half2*)&u1.y);
        acc.x += e0 * a0.x + e1 * c0.x;
        acc.y += e0 * a0.y + e1 * c0.y;
        acc.z += e0 * a1.x + e1 * c1.x;
        acc.w += e0 * a1.y + e1 * c1.y;
        denom += e0 + e1;
    }
    if (j < deg) {
        int slot0 = start + j;
        int s0 = __ldg(&g_csrc[slot0]);
        float e0 = __ldg(&g_e1[(size_t)slot0 * 4 + h]);
        uint2 u0 = *(const uint2*)&g_h1h[(size_t)s0 * F1 + g * 4];
        float2 a0 = __half22float2(*(const __half2*)&u0.x);
        float2 a1 = __half22float2(*(const __half2*)&u0.y);
        acc.x += e0 * a0.x; acc.y += e0 * a0.y;
        acc.z += e0 * a1.x; acc.w += e0 * a1.y;
        denom += e0;
    }
    float inv = 1.0f / fmaxf(denom, 1e-16f);
    float4 bv = *(const float4*)&b1[g * 4];
    float4 r;
    r.x = acc.x * inv + bv.x;
    r.y = acc.y * inv + bv.y;
    r.z = acc.z * inv + bv.z;
    r.w = acc.w * inv + bv.w;
    r.x = r.x > 0.f ? r.x : expm1f(r.x);
    r.y = r.y > 0.f ? r.y : expm1f(r.y);
    r.z = r.z > 0.f ? r.z : expm1f(r.z);
    r.w = r.w > 0.f ? r.w : expm1f(r.w);
    *(float4*)&g_out1[(size_t)node * F1 + g * 4] = r;
}

// ---------------- pure-gather aggregate, layer 2 (fp32 rows) --------------
__global__ void k_agg2_csr(const float* __restrict__ b2, float* __restrict__ out) {
    int node = blockIdx.x * 16 + (threadIdx.x >> 4);
    int c    = threadIdx.x & 15;
    int start = g_start[node];
    int deg   = g_cnt[node];

    float4 acc = make_float4(0.f, 0.f, 0.f, 0.f);
    float denom = 0.f;
    int j = 0;
    for (; j + 2 <= deg; j += 2) {
        int slot0 = start + j, slot1 = start + j + 1;
        int s0 = __ldg(&g_csrc[slot0]);
        int s1 = __ldg(&g_csrc[slot1]);
        float e0 = __ldg(&g_e2[slot0]);
        float e1 = __ldg(&g_e2[slot1]);
        float4 v0 = *(const float4*)&g_h2[(size_t)s0 * OUT + c * 4];
        float4 v1 = *(const float4*)&g_h2[(size_t)s1 * OUT + c * 4];
        acc.x += e0 * v0.x + e1 * v1.x;
        acc.y += e0 * v0.y + e1 * v1.y;
        acc.z += e0 * v0.z + e1 * v1.z;
        acc.w += e0 * v0.w + e1 * v1.w;
        denom += e0 + e1;
    }
    if (j < deg) {
        int slot0 = start + j;
        int s0 = __ldg(&g_csrc[slot0]);
        float e0 = __ldg(&g_e2[slot0]);
        float4 v0 = *(const float4*)&g_h2[(size_t)s0 * OUT + c * 4];
        acc.x += e0 * v0.x; acc.y += e0 * v0.y;
        acc.z += e0 * v0.z; acc.w += e0 * v0.w;
        denom += e0;
    }
    float inv = 1.0f / fmaxf(denom, 1e-16f);
    float4 bv = *(const float4*)&b2[c * 4];
    float4 r;
    r.x = acc.x * inv + bv.x;
    r.y = acc.y * inv + bv.y;
    r.z = acc.z * inv + bv.z;
    r.w = acc.w * inv + bv.w;
    *(float4*)&out[(size_t)node * OUT + c * 4] = r;
}

// ---------------- launch ----------------
extern "C" void kernel_launch(void* const* d_in, const int* in_sizes, int n_in,
                              void* d_out, int out_size) {
    const float* x     = (const float*)d_in[0];
    const int*   ei    = (const int*)d_in[1];
    const float* W1    = (const float*)d_in[2];
    const float* asrc1 = (const float*)d_in[3];
    const float* adst1 = (const float*)d_in[4];
    const float* b1    = (const float*)d_in[5];
    const float* W2    = (const float*)d_in[6];
    const float* asrc2 = (const float*)d_in[7];
    const float* adst2 = (const float*)d_in[8];
    const float* b2    = (const float*)d_in[9];
    float* out = (float*)d_out;

    __half* h1h;  cudaGetSymbolAddress((void**)&h1h, g_h1h);
    float*  out1; cudaGetSymbolAddress((void**)&out1, g_out1);
    float*  h2;   cudaGetSymbolAddress((void**)&h2, g_h2);

    const int T = 256;

    // decode + histogram + single-pass scan
    k_detect<<<(NN + 1023) / 1024, 1024>>>(ei);
    k_convert_hist<<<(ET + T - 1) / T, T>>>(ei);
    k_scan_all<<<SCAN_B, 1024>>>();

    // attention coefficients from x (independent of GEMM), then fused scatter+exp1
    k_w1a<<<1, 1024>>>(W1, asrc1, adst1);
    k_al1x<<<(NN + 31) / 32, 256>>>(x);
    k_scatter_exp1<<<(ET + T - 1) / T, T>>>();

    // layer 1
    gemm_f16x<<<dim3(F1 / TBN, (NN + TBM - 1) / TBM), 256>>>(x, W1, (float*)nullptr, h1h, NN, F1, INCH);
    k_agg1_csr<<<NN / 4, 256>>>(b1);

    // layer 2
    gemm_f16x<<<dim3(OUT / TBN, (NN + TBM - 1) / TBM), 256>>>(out1, W2, h2, (__half*)nullptr, NN, OUT, F1);
    k_al2<<<(NN + T - 1) / T, T>>>(asrc2, adst2);
    k_exp2<<<(ET + T - 1) / T, T>>>();
    k_agg2_csr<<<NN / 16, 256>>>(b2, out);
}